// round 1
// baseline (speedup 1.0000x reference)
#include <cuda_runtime.h>

#define NN 100000
#define NE 200000
#define NG 5000
#define LD 64
static constexpr float EPSV = 1e-5f;

// ---------------- device scratch (static, allocation-free) ----------------
__device__ __align__(16) float g_agg1[NN * 32];
__device__ __align__(16) float g_h1  [NN * 32];
__device__ __align__(16) float g_h1n [NN * 32];
__device__ __align__(16) float g_agg2[NN * 64];
__device__ __align__(16) float g_h2  [NN * 64];
__device__ __align__(16) float g_pooled[NG * 64];
__device__ float g_cnt[NG];
__device__ int   g_deg[NN];
__device__ float g_stat1[64];    // [0..31]=sum, [32..63]=sumsq
__device__ float g_stat2[128];   // [0..63]=sum, [64..127]=sumsq
__device__ __align__(16) float g_We1t[128 * 32];   // [k=i*8+f][o]
__device__ __align__(16) float g_We2t[256 * 64];   // [k=i*8+f][o]
__device__ __align__(16) float g_Wt1[64 * 128];    // Wf1 transposed [i][o]
__device__ __align__(16) float g_Wt2[128 * 128];   // Wf2 transposed [i][o]

// ---------------- init: zero all accumulators ----------------
__global__ void k_init() {
    int idx = blockIdx.x * blockDim.x + threadIdx.x;
    int stride = gridDim.x * blockDim.x;
    for (int j = idx; j < NN * 64; j += stride) g_agg2[j] = 0.f;
    for (int j = idx; j < NN * 32; j += stride) g_agg1[j] = 0.f;
    for (int j = idx; j < NG * 64; j += stride) g_pooled[j] = 0.f;
    for (int j = idx; j < NG;      j += stride) g_cnt[j] = 0.f;
    for (int j = idx; j < NN;      j += stride) g_deg[j] = 0;
    if (idx < 64)  g_stat1[idx] = 0.f;
    if (idx < 128) g_stat2[idx] = 0.f;
}

// ---------------- weight prep: reshape/transpose once per launch ----------------
__global__ void k_prep(const float* __restrict__ We1, const float* __restrict__ We2,
                       const float* __restrict__ Wf1, const float* __restrict__ Wf2) {
    int idx = blockIdx.x * blockDim.x + threadIdx.x;
    // We1t: [k=128][o=32], We1 is [32*16, 8] rows indexed (o*16+i)
    if (idx < 128 * 32) {
        int k = idx >> 5, o = idx & 31;
        int i = k >> 3, f = k & 7;
        g_We1t[idx] = We1[((o << 4) + i) * 8 + f];
    }
    int j = idx - 128 * 32;
    if (j >= 0 && j < 256 * 64) {
        int k = j >> 6, o = j & 63;
        int i = k >> 3, f = k & 7;
        g_We2t[j] = We2[((o << 5) + i) * 8 + f];
    }
    int p = idx - (128 * 32 + 256 * 64);
    if (p >= 0 && p < 64 * 128) {
        int i = p >> 7, o = p & 127;
        g_Wt1[p] = Wf1[o * 64 + i];
    }
    int q = idx - (128 * 32 + 256 * 64 + 64 * 128);
    if (q >= 0 && q < 128 * 128) {
        int i = q >> 7, o = q & 127;
        g_Wt2[q] = Wf2[o * 128 + i];
    }
}

// ---------------- out-degree count ----------------
__global__ void k_deg(const int* __restrict__ ei) {
    int e = blockIdx.x * blockDim.x + threadIdx.x;
    if (e < NE) atomicAdd(&g_deg[ei[e]], 1);
}

// ---------------- edge layer 1: msg = (x_src ⊗ ea) @ W1', scatter to agg1 ----------------
__global__ __launch_bounds__(128) void k_edge1(const int* __restrict__ ei,
                                               const float* __restrict__ x,
                                               const float* __restrict__ ea) {
    __shared__ float Ws[128 * 32];   // 16 KB
    int tid = threadIdx.x;
    #pragma unroll
    for (int t = tid; t < 128 * 32; t += 128) Ws[t] = g_We1t[t];
    __syncthreads();

    int e = blockIdx.x * 128 + tid;
    if (e >= NE) return;
    int s = ei[e], d = ei[NE + e];
    float nrm = 1.0f / (float)g_deg[s];

    float eav[8];
    const float4* ep = (const float4*)(ea + (size_t)e * 8);
    float4 e0 = ep[0], e1 = ep[1];
    eav[0] = e0.x; eav[1] = e0.y; eav[2] = e0.z; eav[3] = e0.w;
    eav[4] = e1.x; eav[5] = e1.y; eav[6] = e1.z; eav[7] = e1.w;

    float4 acc[8];
    #pragma unroll
    for (int q = 0; q < 8; q++) acc[q] = make_float4(0.f, 0.f, 0.f, 0.f);

    const float* xr = x + (size_t)s * 16;
    for (int i = 0; i < 16; i++) {
        float hi = __ldg(xr + i) * nrm;
        #pragma unroll
        for (int f = 0; f < 8; f++) {
            float z = hi * eav[f];
            const float4* w = (const float4*)(Ws + ((i << 3) + f) * 32);
            #pragma unroll
            for (int q = 0; q < 8; q++) {
                float4 wv = w[q];
                acc[q].x += z * wv.x; acc[q].y += z * wv.y;
                acc[q].z += z * wv.z; acc[q].w += z * wv.w;
            }
        }
    }
    float* ag = g_agg1 + (size_t)d * 32;
    #pragma unroll
    for (int q = 0; q < 8; q++) {
        atomicAdd(ag + 4 * q + 0, acc[q].x);
        atomicAdd(ag + 4 * q + 1, acc[q].y);
        atomicAdd(ag + 4 * q + 2, acc[q].z);
        atomicAdd(ag + 4 * q + 3, acc[q].w);
    }
}

// ---------------- edge layer 2 ----------------
__global__ __launch_bounds__(128) void k_edge2(const int* __restrict__ ei,
                                               const float* __restrict__ ea) {
    extern __shared__ float Ws[];   // 256*64 floats = 64 KB
    int tid = threadIdx.x;
    for (int t = tid; t < 256 * 64; t += 128) Ws[t] = g_We2t[t];
    __syncthreads();

    int e = blockIdx.x * 128 + tid;
    if (e >= NE) return;
    int s = ei[e], d = ei[NE + e];
    float nrm = 1.0f / (float)g_deg[s];

    float eav[8];
    const float4* ep = (const float4*)(ea + (size_t)e * 8);
    float4 e0 = ep[0], e1 = ep[1];
    eav[0] = e0.x; eav[1] = e0.y; eav[2] = e0.z; eav[3] = e0.w;
    eav[4] = e1.x; eav[5] = e1.y; eav[6] = e1.z; eav[7] = e1.w;

    float4 acc[16];
    #pragma unroll
    for (int q = 0; q < 16; q++) acc[q] = make_float4(0.f, 0.f, 0.f, 0.f);

    const float* hr = g_h1n + (size_t)s * 32;
    for (int i = 0; i < 32; i++) {
        float hi = __ldg(hr + i) * nrm;
        #pragma unroll
        for (int f = 0; f < 8; f++) {
            float z = hi * eav[f];
            const float4* w = (const float4*)(Ws + ((i << 3) + f) * 64);
            #pragma unroll
            for (int q = 0; q < 16; q++) {
                float4 wv = w[q];
                acc[q].x += z * wv.x; acc[q].y += z * wv.y;
                acc[q].z += z * wv.z; acc[q].w += z * wv.w;
            }
        }
    }
    float* ag = g_agg2 + (size_t)d * 64;
    #pragma unroll
    for (int q = 0; q < 16; q++) {
        atomicAdd(ag + 4 * q + 0, acc[q].x);
        atomicAdd(ag + 4 * q + 1, acc[q].y);
        atomicAdd(ag + 4 * q + 2, acc[q].z);
        atomicAdd(ag + 4 * q + 3, acc[q].w);
    }
}

// ---------------- node layer 1: h1 = agg1 + b1 + x @ Wr1.T ----------------
__global__ __launch_bounds__(128) void k_node1(const float* __restrict__ x,
                                               const float* __restrict__ b1,
                                               const float* __restrict__ Wr1) {
    __shared__ float Ws[32 * 16];
    __shared__ float bs[32];
    int tid = threadIdx.x;
    for (int t = tid; t < 512; t += 128) Ws[t] = Wr1[t];
    if (tid < 32) bs[tid] = b1[tid];
    __syncthreads();

    int n = blockIdx.x * 128 + tid;
    if (n >= NN) return;
    float xv[16];
    const float4* xp = (const float4*)(x + (size_t)n * 16);
    #pragma unroll
    for (int q = 0; q < 4; q++) {
        float4 v = xp[q];
        xv[4 * q + 0] = v.x; xv[4 * q + 1] = v.y; xv[4 * q + 2] = v.z; xv[4 * q + 3] = v.w;
    }
    const float4* ap = (const float4*)(g_agg1 + (size_t)n * 32);
    float4* hp = (float4*)(g_h1 + (size_t)n * 32);
    for (int o4 = 0; o4 < 8; o4++) {
        float4 a = ap[o4];
        float rr[4];
        #pragma unroll
        for (int jj = 0; jj < 4; jj++) {
            int o = o4 * 4 + jj;
            float sum = 0.f;
            #pragma unroll
            for (int i = 0; i < 16; i++) sum += xv[i] * Ws[o * 16 + i];
            rr[jj] = sum + bs[o];
        }
        hp[o4] = make_float4(a.x + rr[0], a.y + rr[1], a.z + rr[2], a.w + rr[3]);
    }
}

// ---------------- node layer 2: h2 = agg2 + b2 + h1n @ Wr2.T ----------------
__global__ __launch_bounds__(128) void k_node2(const float* __restrict__ b2,
                                               const float* __restrict__ Wr2) {
    __shared__ float Ws[64 * 32];   // 8 KB
    __shared__ float bs[64];
    int tid = threadIdx.x;
    for (int t = tid; t < 64 * 32; t += 128) Ws[t] = Wr2[t];
    if (tid < 64) bs[tid] = b2[tid];
    __syncthreads();

    int n = blockIdx.x * 128 + tid;
    if (n >= NN) return;
    float xv[32];
    const float4* xp = (const float4*)(g_h1n + (size_t)n * 32);
    #pragma unroll
    for (int q = 0; q < 8; q++) {
        float4 v = xp[q];
        xv[4 * q + 0] = v.x; xv[4 * q + 1] = v.y; xv[4 * q + 2] = v.z; xv[4 * q + 3] = v.w;
    }
    const float4* ap = (const float4*)(g_agg2 + (size_t)n * 64);
    float4* hp = (float4*)(g_h2 + (size_t)n * 64);
    for (int o4 = 0; o4 < 16; o4++) {
        float4 a = ap[o4];
        float rr[4];
        #pragma unroll
        for (int jj = 0; jj < 4; jj++) {
            int o = o4 * 4 + jj;
            float sum = 0.f;
            #pragma unroll
            for (int i = 0; i < 32; i++) sum += xv[i] * Ws[o * 32 + i];
            rr[jj] = sum + bs[o];
        }
        hp[o4] = make_float4(a.x + rr[0], a.y + rr[1], a.z + rr[2], a.w + rr[3]);
    }
}

// ---------------- per-channel sum/sumsq reduction ----------------
template <int C>
__device__ __forceinline__ void stats_impl(const float* __restrict__ src,
                                           float* __restrict__ stat, int rows) {
    __shared__ float sA[256], sB[256];
    int tid = threadIdx.x;
    int gidx = blockIdx.x * 256 + tid;
    int c = gidx % C;
    int r = gidx / C;
    int rstep = (gridDim.x * 256) / C;
    float s = 0.f, q = 0.f;
    for (; r < rows; r += rstep) {
        float v = src[(size_t)r * C + c];
        s += v; q += v * v;
    }
    sA[tid] = s; sB[tid] = q;
    __syncthreads();
    for (int off = 128; off >= C; off >>= 1) {
        if (tid < off) { sA[tid] += sA[tid + off]; sB[tid] += sB[tid + off]; }
        __syncthreads();
    }
    if (tid < C) { atomicAdd(&stat[tid], sA[tid]); atomicAdd(&stat[C + tid], sB[tid]); }
}
__global__ void k_stats1() { stats_impl<32>(g_h1, g_stat1, NN); }
__global__ void k_stats2() { stats_impl<64>(g_h2, g_stat2, NN); }

// ---------------- BN1 apply + relu -> h1n ----------------
__global__ void k_bn1(const float* __restrict__ g1, const float* __restrict__ be1) {
    int idx = blockIdx.x * blockDim.x + threadIdx.x;
    if (idx >= NN * 32) return;
    int c = idx & 31;
    const float invN = 1.0f / (float)NN;
    float mu = g_stat1[c] * invN;
    float var = g_stat1[32 + c] * invN - mu * mu;
    float rs = rsqrtf(var + EPSV);
    float v = (g_h1[idx] - mu) * rs * g1[c] + be1[c];
    g_h1n[idx] = fmaxf(v, 0.f);
}

// ---------------- BN2 apply + relu + segment-sum pooling ----------------
__global__ void k_bn2pool(const float* __restrict__ g2, const float* __restrict__ be2,
                          const int* __restrict__ batch) {
    int idx = blockIdx.x * blockDim.x + threadIdx.x;
    if (idx >= NN * 64) return;
    int c = idx & 63;
    int n = idx >> 6;
    const float invN = 1.0f / (float)NN;
    float mu = g_stat2[c] * invN;
    float var = g_stat2[64 + c] * invN - mu * mu;
    float rs = rsqrtf(var + EPSV);
    float v = (g_h2[idx] - mu) * rs * g2[c] + be2[c];
    v = fmaxf(v, 0.f);
    int b = batch[n];
    atomicAdd(&g_pooled[b * 64 + c], v);
    if (c == 0) atomicAdd(&g_cnt[b], 1.0f);
}

// ---------------- final MLP: 8 graphs per block ----------------
__global__ __launch_bounds__(128) void k_fc(const float* __restrict__ bf1,
                                            const float* __restrict__ bf2,
                                            float* __restrict__ out) {
    __shared__ float pm[8][64];
    __shared__ float hid[8][128];
    int tid = threadIdx.x;
    int g0 = blockIdx.x * 8;
    for (int t = tid; t < 512; t += 128) {
        int gg = t >> 6, i = t & 63;
        int g = g0 + gg;
        pm[gg][i] = g_pooled[g * 64 + i] / fmaxf(g_cnt[g], 1.0f);
    }
    __syncthreads();

    float acc[8];
    float b = bf1[tid];
    #pragma unroll
    for (int gg = 0; gg < 8; gg++) acc[gg] = b;
    for (int i = 0; i < 64; i++) {
        float w = g_Wt1[i * 128 + tid];
        #pragma unroll
        for (int gg = 0; gg < 8; gg++) acc[gg] += w * pm[gg][i];
    }
    #pragma unroll
    for (int gg = 0; gg < 8; gg++) hid[gg][tid] = fmaxf(acc[gg], 0.f);
    __syncthreads();

    float b2v = bf2[tid];
    #pragma unroll
    for (int gg = 0; gg < 8; gg++) acc[gg] = b2v;
    for (int i = 0; i < 128; i++) {
        float w = g_Wt2[i * 128 + tid];
        #pragma unroll
        for (int gg = 0; gg < 8; gg++) acc[gg] += w * hid[gg][i];
    }
    #pragma unroll
    for (int gg = 0; gg < 8; gg++) {
        int g = g0 + gg;
        if (tid < 64) out[g * 64 + tid] = acc[gg];                      // mu_z
        else          out[NG * 64 + g * 64 + (tid - 64)] = acc[gg];     // log_sigma
    }
}

// ---------------- launch ----------------
extern "C" void kernel_launch(void* const* d_in, const int* in_sizes, int n_in,
                              void* d_out, int out_size) {
    const float* x    = (const float*)d_in[0];
    const int*   ei   = (const int*)  d_in[1];
    const float* ea   = (const float*)d_in[2];
    const int*   batch= (const int*)  d_in[3];
    const float* We1  = (const float*)d_in[4];
    const float* b1   = (const float*)d_in[5];
    const float* Wr1  = (const float*)d_in[6];
    const float* g1   = (const float*)d_in[7];
    const float* be1  = (const float*)d_in[8];
    const float* We2  = (const float*)d_in[9];
    const float* b2   = (const float*)d_in[10];
    const float* Wr2  = (const float*)d_in[11];
    const float* g2   = (const float*)d_in[12];
    const float* be2  = (const float*)d_in[13];
    const float* Wf1  = (const float*)d_in[14];
    const float* bf1  = (const float*)d_in[15];
    const float* Wf2  = (const float*)d_in[16];
    const float* bf2  = (const float*)d_in[17];
    float* out = (float*)d_out;

    cudaFuncSetAttribute(k_edge2, cudaFuncAttributeMaxDynamicSharedMemorySize, 256 * 64 * 4);

    k_init<<<512, 256>>>();
    k_prep<<<(128 * 32 + 256 * 64 + 64 * 128 + 128 * 128 + 255) / 256, 256>>>(We1, We2, Wf1, Wf2);
    k_deg<<<(NE + 255) / 256, 256>>>(ei);
    k_edge1<<<(NE + 127) / 128, 128>>>(ei, x, ea);
    k_node1<<<(NN + 127) / 128, 128>>>(x, b1, Wr1);
    k_stats1<<<128, 256>>>();
    k_bn1<<<(NN * 32 + 255) / 256, 256>>>(g1, be1);
    k_edge2<<<(NE + 127) / 128, 128, 256 * 64 * 4>>>(ei, ea);
    k_node2<<<(NN + 127) / 128, 128>>>(b2, Wr2);
    k_stats2<<<128, 256>>>();
    k_bn2pool<<<(NN * 64 + 255) / 256, 256>>>(g2, be2, batch);
    k_fc<<<NG / 8, 128>>>(bf1, bf2, out);
}

// round 2
// speedup vs baseline: 1.3422x; 1.3422x over previous
#include <cuda_runtime.h>

#define NN 100000
#define NE 200000
#define NG 5000
#define LD 64
static constexpr float EPSV = 1e-5f;

// ---------------- device scratch (static, allocation-free) ----------------
__device__ __align__(16) float g_agg1[NN * 32];
__device__ __align__(16) float g_h1  [NN * 32];
__device__ __align__(16) float g_h1n [NN * 32];
__device__ __align__(16) float g_agg2[NN * 64];
__device__ __align__(16) float g_h2  [NN * 64];
__device__ __align__(16) float g_pooled[NG * 64];
__device__ float g_cnt[NG];
__device__ int   g_deg[NN];
__device__ float g_stat1[64];    // [0..31]=sum, [32..63]=sumsq
__device__ float g_stat2[128];   // [0..63]=sum, [64..127]=sumsq
__device__ __align__(16) float g_Wp1[16 * 256];    // [i][f*32+o]
__device__ __align__(16) float g_Wp2[32 * 512];    // [i][f*64+o]
__device__ __align__(16) float g_Wt1[64 * 128];    // Wf1 transposed [i][o]
__device__ __align__(16) float g_Wt2[128 * 128];   // Wf2 transposed [i][o]
__device__ __align__(16) float g_P1[NN * 256];     // node table layer 1
__device__ __align__(16) float g_P2[(size_t)NN * 512]; // node table layer 2

// vector global reduction
__device__ __forceinline__ void red_v4(float* p, float4 v) {
    asm volatile("red.global.add.v4.f32 [%0], {%1,%2,%3,%4};"
                 :: "l"(p), "f"(v.x), "f"(v.y), "f"(v.z), "f"(v.w) : "memory");
}

// ---------------- init: zero all accumulators ----------------
__global__ void k_init() {
    int idx = blockIdx.x * blockDim.x + threadIdx.x;
    int stride = gridDim.x * blockDim.x;
    for (int j = idx; j < NN * 64; j += stride) g_agg2[j] = 0.f;
    for (int j = idx; j < NN * 32; j += stride) g_agg1[j] = 0.f;
    for (int j = idx; j < NG * 64; j += stride) g_pooled[j] = 0.f;
    for (int j = idx; j < NG;      j += stride) g_cnt[j] = 0.f;
    for (int j = idx; j < NN;      j += stride) g_deg[j] = 0;
    if (idx < 64)  g_stat1[idx] = 0.f;
    if (idx < 128) g_stat2[idx] = 0.f;
}

// ---------------- weight prep ----------------
__global__ void k_prep(const float* __restrict__ We1, const float* __restrict__ We2,
                       const float* __restrict__ Wf1, const float* __restrict__ Wf2) {
    int idx = blockIdx.x * blockDim.x + threadIdx.x;
    if (idx < 16 * 256) {
        int i = idx >> 8, col = idx & 255;
        int f = col >> 5, o = col & 31;
        g_Wp1[idx] = We1[((o << 4) + i) * 8 + f];
    }
    int j = idx - 16 * 256;
    if (j >= 0 && j < 32 * 512) {
        int i = j >> 9, col = j & 511;
        int f = col >> 6, o = col & 63;
        g_Wp2[j] = We2[((o << 5) + i) * 8 + f];
    }
    int p = idx - (16 * 256 + 32 * 512);
    if (p >= 0 && p < 64 * 128) {
        int i = p >> 7, o = p & 127;
        g_Wt1[p] = Wf1[o * 64 + i];
    }
    int q = idx - (16 * 256 + 32 * 512 + 64 * 128);
    if (q >= 0 && q < 128 * 128) {
        int i = q >> 7, o = q & 127;
        g_Wt2[q] = Wf2[o * 128 + i];
    }
}

// ---------------- out-degree count ----------------
__global__ void k_deg(const int* __restrict__ ei) {
    int e = blockIdx.x * blockDim.x + threadIdx.x;
    if (e < NE) atomicAdd(&g_deg[ei[e]], 1);
}

// ---------------- node GEMM 1: P1 = (x*nrm) @ Wp1   [100000 x 16] @ [16 x 256]
__global__ __launch_bounds__(256) void k_gemm1(const float* __restrict__ x) {
    __shared__ float Wsm[16 * 256];   // 16 KB
    __shared__ float Xsm[64 * 16];    // 4 KB
    int tid = threadIdx.x;
    for (int t = tid; t < 16 * 256; t += 256) Wsm[t] = g_Wp1[t];
    int n0 = blockIdx.x * 64;
    for (int t = tid; t < 64 * 16; t += 256) {
        int n = t >> 4, k = t & 15;
        int gn = n0 + n;
        float v = 0.f;
        if (gn < NN) {
            int dg = g_deg[gn];
            float nrm = dg > 0 ? 1.f / (float)dg : 0.f;
            v = x[(size_t)gn * 16 + k] * nrm;
        }
        Xsm[t] = v;
    }
    __syncthreads();

    int tx = tid & 31, ty = tid >> 5;   // ty: 0..7, each owns 8 node rows
    float4 a0[8], a1[8];
    #pragma unroll
    for (int m = 0; m < 8; m++) { a0[m] = make_float4(0,0,0,0); a1[m] = make_float4(0,0,0,0); }

    #pragma unroll
    for (int k = 0; k < 16; k++) {
        float4 w0 = *(const float4*)(Wsm + k * 256 + tx * 4);
        float4 w1 = *(const float4*)(Wsm + k * 256 + 128 + tx * 4);
        #pragma unroll
        for (int m = 0; m < 8; m++) {
            float xv = Xsm[(ty * 8 + m) * 16 + k];
            a0[m].x += xv * w0.x; a0[m].y += xv * w0.y; a0[m].z += xv * w0.z; a0[m].w += xv * w0.w;
            a1[m].x += xv * w1.x; a1[m].y += xv * w1.y; a1[m].z += xv * w1.z; a1[m].w += xv * w1.w;
        }
    }
    #pragma unroll
    for (int m = 0; m < 8; m++) {
        int gn = n0 + ty * 8 + m;
        if (gn < NN) {
            *(float4*)(g_P1 + (size_t)gn * 256 + tx * 4)       = a0[m];
            *(float4*)(g_P1 + (size_t)gn * 256 + 128 + tx * 4) = a1[m];
        }
    }
}

// ---------------- node GEMM 2: P2 = (h1n*nrm) @ Wp2   [100000 x 32] @ [32 x 512]
__global__ __launch_bounds__(256) void k_gemm2() {
    extern __shared__ float sm[];
    float* Wsm = sm;              // 32*512 = 64 KB
    float* Xsm = sm + 32 * 512;   // 32*32  = 4 KB
    int tid = threadIdx.x;
    for (int t = tid; t < 32 * 512; t += 256) Wsm[t] = g_Wp2[t];
    int n0 = blockIdx.x * 32;
    for (int t = tid; t < 32 * 32; t += 256) {
        int n = t >> 5, k = t & 31;
        int gn = n0 + n;
        float v = 0.f;
        if (gn < NN) {
            int dg = g_deg[gn];
            float nrm = dg > 0 ? 1.f / (float)dg : 0.f;
            v = g_h1n[(size_t)gn * 32 + k] * nrm;
        }
        Xsm[t] = v;
    }
    __syncthreads();

    int tx = tid & 63, ty = tid >> 6;   // ty: 0..3, each owns 8 node rows
    float4 a0[8], a1[8];
    #pragma unroll
    for (int m = 0; m < 8; m++) { a0[m] = make_float4(0,0,0,0); a1[m] = make_float4(0,0,0,0); }

    #pragma unroll
    for (int k = 0; k < 32; k++) {
        float4 w0 = *(const float4*)(Wsm + k * 512 + tx * 4);
        float4 w1 = *(const float4*)(Wsm + k * 512 + 256 + tx * 4);
        #pragma unroll
        for (int m = 0; m < 8; m++) {
            float xv = Xsm[(ty * 8 + m) * 32 + k];
            a0[m].x += xv * w0.x; a0[m].y += xv * w0.y; a0[m].z += xv * w0.z; a0[m].w += xv * w0.w;
            a1[m].x += xv * w1.x; a1[m].y += xv * w1.y; a1[m].z += xv * w1.z; a1[m].w += xv * w1.w;
        }
    }
    #pragma unroll
    for (int m = 0; m < 8; m++) {
        int gn = n0 + ty * 8 + m;
        if (gn < NN) {
            *(float4*)(g_P2 + (size_t)gn * 512 + tx * 4)       = a0[m];
            *(float4*)(g_P2 + (size_t)gn * 512 + 256 + tx * 4) = a1[m];
        }
    }
}

// ---------------- edge gather 1: msg = Sum_f ea[f]*P1[src, f*32+c], scatter to agg1
__global__ __launch_bounds__(256) void k_edge1g(const int* __restrict__ ei,
                                                const float* __restrict__ ea) {
    int idx = blockIdx.x * 256 + threadIdx.x;
    if (idx >= NE * 8) return;
    int e = idx >> 3, q = idx & 7;
    int s = ei[e], d = ei[NE + e];
    const float* Pr = g_P1 + (size_t)s * 256 + q * 4;
    const float* er = ea + (size_t)e * 8;
    float4 a = make_float4(0, 0, 0, 0);
    #pragma unroll
    for (int f = 0; f < 8; f++) {
        float ev = __ldg(er + f);
        float4 p = __ldg((const float4*)(Pr + f * 32));
        a.x += ev * p.x; a.y += ev * p.y; a.z += ev * p.z; a.w += ev * p.w;
    }
    red_v4(g_agg1 + (size_t)d * 32 + q * 4, a);
}

// ---------------- edge gather 2 ----------------
__global__ __launch_bounds__(256) void k_edge2g(const int* __restrict__ ei,
                                                const float* __restrict__ ea) {
    int idx = blockIdx.x * 256 + threadIdx.x;
    if (idx >= NE * 16) return;
    int e = idx >> 4, q = idx & 15;
    int s = ei[e], d = ei[NE + e];
    const float* Pr = g_P2 + (size_t)s * 512 + q * 4;
    const float* er = ea + (size_t)e * 8;
    float4 a = make_float4(0, 0, 0, 0);
    #pragma unroll
    for (int f = 0; f < 8; f++) {
        float ev = __ldg(er + f);
        float4 p = __ldg((const float4*)(Pr + f * 64));
        a.x += ev * p.x; a.y += ev * p.y; a.z += ev * p.z; a.w += ev * p.w;
    }
    red_v4(g_agg2 + (size_t)d * 64 + q * 4, a);
}

// ---------------- node layer 1: h1 = agg1 + b1 + x @ Wr1.T ----------------
__global__ __launch_bounds__(128) void k_node1(const float* __restrict__ x,
                                               const float* __restrict__ b1,
                                               const float* __restrict__ Wr1) {
    __shared__ float Ws[32 * 16];
    __shared__ float bs[32];
    int tid = threadIdx.x;
    for (int t = tid; t < 512; t += 128) Ws[t] = Wr1[t];
    if (tid < 32) bs[tid] = b1[tid];
    __syncthreads();

    int n = blockIdx.x * 128 + tid;
    if (n >= NN) return;
    float xv[16];
    const float4* xp = (const float4*)(x + (size_t)n * 16);
    #pragma unroll
    for (int q = 0; q < 4; q++) {
        float4 v = xp[q];
        xv[4 * q + 0] = v.x; xv[4 * q + 1] = v.y; xv[4 * q + 2] = v.z; xv[4 * q + 3] = v.w;
    }
    const float4* ap = (const float4*)(g_agg1 + (size_t)n * 32);
    float4* hp = (float4*)(g_h1 + (size_t)n * 32);
    for (int o4 = 0; o4 < 8; o4++) {
        float4 a = ap[o4];
        float rr[4];
        #pragma unroll
        for (int jj = 0; jj < 4; jj++) {
            int o = o4 * 4 + jj;
            float sum = 0.f;
            #pragma unroll
            for (int i = 0; i < 16; i++) sum += xv[i] * Ws[o * 16 + i];
            rr[jj] = sum + bs[o];
        }
        hp[o4] = make_float4(a.x + rr[0], a.y + rr[1], a.z + rr[2], a.w + rr[3]);
    }
}

// ---------------- node layer 2: h2 = agg2 + b2 + h1n @ Wr2.T ----------------
__global__ __launch_bounds__(128) void k_node2(const float* __restrict__ b2,
                                               const float* __restrict__ Wr2) {
    __shared__ float Ws[64 * 32];
    __shared__ float bs[64];
    int tid = threadIdx.x;
    for (int t = tid; t < 64 * 32; t += 128) Ws[t] = Wr2[t];
    if (tid < 64) bs[tid] = b2[tid];
    __syncthreads();

    int n = blockIdx.x * 128 + tid;
    if (n >= NN) return;
    float xv[32];
    const float4* xp = (const float4*)(g_h1n + (size_t)n * 32);
    #pragma unroll
    for (int q = 0; q < 8; q++) {
        float4 v = xp[q];
        xv[4 * q + 0] = v.x; xv[4 * q + 1] = v.y; xv[4 * q + 2] = v.z; xv[4 * q + 3] = v.w;
    }
    const float4* ap = (const float4*)(g_agg2 + (size_t)n * 64);
    float4* hp = (float4*)(g_h2 + (size_t)n * 64);
    for (int o4 = 0; o4 < 16; o4++) {
        float4 a = ap[o4];
        float rr[4];
        #pragma unroll
        for (int jj = 0; jj < 4; jj++) {
            int o = o4 * 4 + jj;
            float sum = 0.f;
            #pragma unroll
            for (int i = 0; i < 32; i++) sum += xv[i] * Ws[o * 32 + i];
            rr[jj] = sum + bs[o];
        }
        hp[o4] = make_float4(a.x + rr[0], a.y + rr[1], a.z + rr[2], a.w + rr[3]);
    }
}

// ---------------- per-channel sum/sumsq reduction ----------------
template <int C>
__device__ __forceinline__ void stats_impl(const float* __restrict__ src,
                                           float* __restrict__ stat, int rows) {
    __shared__ float sA[256], sB[256];
    int tid = threadIdx.x;
    int gidx = blockIdx.x * 256 + tid;
    int c = gidx % C;
    int r = gidx / C;
    int rstep = (gridDim.x * 256) / C;
    float s = 0.f, q = 0.f;
    for (; r < rows; r += rstep) {
        float v = src[(size_t)r * C + c];
        s += v; q += v * v;
    }
    sA[tid] = s; sB[tid] = q;
    __syncthreads();
    for (int off = 128; off >= C; off >>= 1) {
        if (tid < off) { sA[tid] += sA[tid + off]; sB[tid] += sB[tid + off]; }
        __syncthreads();
    }
    if (tid < C) { atomicAdd(&stat[tid], sA[tid]); atomicAdd(&stat[C + tid], sB[tid]); }
}
__global__ void k_stats1() { stats_impl<32>(g_h1, g_stat1, NN); }
__global__ void k_stats2() { stats_impl<64>(g_h2, g_stat2, NN); }

// ---------------- BN1 apply + relu -> h1n ----------------
__global__ void k_bn1(const float* __restrict__ g1, const float* __restrict__ be1) {
    int idx = blockIdx.x * blockDim.x + threadIdx.x;
    if (idx >= NN * 32) return;
    int c = idx & 31;
    const float invN = 1.0f / (float)NN;
    float mu = g_stat1[c] * invN;
    float var = g_stat1[32 + c] * invN - mu * mu;
    float rs = rsqrtf(var + EPSV);
    float v = (g_h1[idx] - mu) * rs * g1[c] + be1[c];
    g_h1n[idx] = fmaxf(v, 0.f);
}

// ---------------- BN2 apply + relu + segment-sum pooling (v4 atomics) -------
__global__ void k_bn2pool(const float* __restrict__ g2, const float* __restrict__ be2,
                          const int* __restrict__ batch) {
    int idx = blockIdx.x * blockDim.x + threadIdx.x;
    if (idx >= NN * 16) return;
    int n = idx >> 4, q = idx & 15;
    const float invN = 1.0f / (float)NN;
    float4 h = *(const float4*)(g_h2 + (size_t)n * 64 + q * 4);
    float4 v;
    float* hv = (float*)&h;
    float* vv = (float*)&v;
    #pragma unroll
    for (int jj = 0; jj < 4; jj++) {
        int c = q * 4 + jj;
        float mu = g_stat2[c] * invN;
        float var = g_stat2[64 + c] * invN - mu * mu;
        float rs = rsqrtf(var + EPSV);
        vv[jj] = fmaxf((hv[jj] - mu) * rs * g2[c] + be2[c], 0.f);
    }
    int b = batch[n];
    red_v4(g_pooled + (size_t)b * 64 + q * 4, v);
    if (q == 0) atomicAdd(&g_cnt[b], 1.0f);
}

// ---------------- final MLP: 8 graphs per block ----------------
__global__ __launch_bounds__(128) void k_fc(const float* __restrict__ bf1,
                                            const float* __restrict__ bf2,
                                            float* __restrict__ out) {
    __shared__ float pm[8][64];
    __shared__ float hid[8][128];
    int tid = threadIdx.x;
    int g0 = blockIdx.x * 8;
    for (int t = tid; t < 512; t += 128) {
        int gg = t >> 6, i = t & 63;
        int g = g0 + gg;
        pm[gg][i] = g_pooled[g * 64 + i] / fmaxf(g_cnt[g], 1.0f);
    }
    __syncthreads();

    float acc[8];
    float b = bf1[tid];
    #pragma unroll
    for (int gg = 0; gg < 8; gg++) acc[gg] = b;
    for (int i = 0; i < 64; i++) {
        float w = g_Wt1[i * 128 + tid];
        #pragma unroll
        for (int gg = 0; gg < 8; gg++) acc[gg] += w * pm[gg][i];
    }
    #pragma unroll
    for (int gg = 0; gg < 8; gg++) hid[gg][tid] = fmaxf(acc[gg], 0.f);
    __syncthreads();

    float b2v = bf2[tid];
    #pragma unroll
    for (int gg = 0; gg < 8; gg++) acc[gg] = b2v;
    for (int i = 0; i < 128; i++) {
        float w = g_Wt2[i * 128 + tid];
        #pragma unroll
        for (int gg = 0; gg < 8; gg++) acc[gg] += w * hid[gg][i];
    }
    #pragma unroll
    for (int gg = 0; gg < 8; gg++) {
        int g = g0 + gg;
        if (tid < 64) out[g * 64 + tid] = acc[gg];                      // mu_z
        else          out[NG * 64 + g * 64 + (tid - 64)] = acc[gg];     // log_sigma
    }
}

// ---------------- launch ----------------
extern "C" void kernel_launch(void* const* d_in, const int* in_sizes, int n_in,
                              void* d_out, int out_size) {
    const float* x    = (const float*)d_in[0];
    const int*   ei   = (const int*)  d_in[1];
    const float* ea   = (const float*)d_in[2];
    const int*   batch= (const int*)  d_in[3];
    const float* We1  = (const float*)d_in[4];
    const float* b1   = (const float*)d_in[5];
    const float* Wr1  = (const float*)d_in[6];
    const float* g1   = (const float*)d_in[7];
    const float* be1  = (const float*)d_in[8];
    const float* We2  = (const float*)d_in[9];
    const float* b2   = (const float*)d_in[10];
    const float* Wr2  = (const float*)d_in[11];
    const float* g2   = (const float*)d_in[12];
    const float* be2  = (const float*)d_in[13];
    const float* Wf1  = (const float*)d_in[14];
    const float* bf1  = (const float*)d_in[15];
    const float* Wf2  = (const float*)d_in[16];
    const float* bf2  = (const float*)d_in[17];
    float* out = (float*)d_out;

    static int smem_set = 0;
    if (!smem_set) {
        cudaFuncSetAttribute(k_gemm2, cudaFuncAttributeMaxDynamicSharedMemorySize,
                             (32 * 512 + 32 * 32) * 4);
        smem_set = 1;
    }

    k_init<<<512, 256>>>();
    k_prep<<<(16 * 256 + 32 * 512 + 64 * 128 + 128 * 128 + 255) / 256, 256>>>(We1, We2, Wf1, Wf2);
    k_deg<<<(NE + 255) / 256, 256>>>(ei);
    k_gemm1<<<(NN + 63) / 64, 256>>>(x);
    k_edge1g<<<(NE * 8 + 255) / 256, 256>>>(ei, ea);
    k_node1<<<(NN + 127) / 128, 128>>>(x, b1, Wr1);
    k_stats1<<<128, 256>>>();
    k_bn1<<<(NN * 32 + 255) / 256, 256>>>(g1, be1);
    k_gemm2<<<(NN + 31) / 32, 256, (32 * 512 + 32 * 32) * 4>>>();
    k_edge2g<<<(NE * 16 + 255) / 256, 256>>>(ei, ea);
    k_node2<<<(NN + 127) / 128, 128>>>(b2, Wr2);
    k_stats2<<<128, 256>>>();
    k_bn2pool<<<(NN * 16 + 255) / 256, 256>>>(g2, be2, batch);
    k_fc<<<NG / 8, 128>>>(bf1, bf2, out);
}

// round 3
// speedup vs baseline: 1.5706x; 1.1702x over previous
#include <cuda_runtime.h>

#define NN 100000
#define NE 200000
#define NG 5000
static constexpr float EPSV = 1e-5f;

// ---------------- device scratch ----------------
__device__ __align__(16) float g_T1[(size_t)NN * 128];   // [n][f*16+i]  51.2 MB
__device__ __align__(16) float g_T2[(size_t)NN * 256];   // [n][f*32+i] 102.4 MB
__device__ __align__(16) float g_h1 [NN * 32];
__device__ __align__(16) float g_h1n[NN * 32];
__device__ __align__(16) float g_h2 [NN * 64];
__device__ __align__(16) float g_pooled[NG * 64];
__device__ float g_cnt[NG];
__device__ int   g_deg[NN];
__device__ float g_stat1[64];    // [0..31]=sum, [32..63]=sumsq
__device__ float g_stat2[128];   // [0..63]=sum, [64..127]=sumsq
__device__ __align__(16) float g_W1p[128 * 32];    // [k=f*16+i][o]
__device__ __align__(16) float g_W2p[256 * 64];    // [k=f*32+i][o]
__device__ __align__(16) float g_Wt1[64 * 128];    // Wf1^T [i][o]
__device__ __align__(16) float g_Wt2[128 * 128];   // Wf2^T [i][o]

__device__ __forceinline__ void red_v4(float* p, float4 v) {
    asm volatile("red.global.add.v4.f32 [%0], {%1,%2,%3,%4};"
                 :: "l"(p), "f"(v.x), "f"(v.y), "f"(v.z), "f"(v.w) : "memory");
}

// ---------------- init small accumulators ----------------
__global__ void k_init() {
    int idx = blockIdx.x * blockDim.x + threadIdx.x;
    int stride = gridDim.x * blockDim.x;
    for (int j = idx; j < NG * 64; j += stride) g_pooled[j] = 0.f;
    for (int j = idx; j < NG;      j += stride) g_cnt[j] = 0.f;
    for (int j = idx; j < NN;      j += stride) g_deg[j] = 0;
    if (idx < 64)  g_stat1[idx] = 0.f;
    if (idx < 128) g_stat2[idx] = 0.f;
}

// ---------------- weight prep ----------------
__global__ void k_prep(const float* __restrict__ We1, const float* __restrict__ We2,
                       const float* __restrict__ Wf1, const float* __restrict__ Wf2) {
    int idx = blockIdx.x * blockDim.x + threadIdx.x;
    if (idx < 128 * 32) {                 // W1p[k=f*16+i][o] = We1[(o*16+i)*8+f]
        int k = idx >> 5, o = idx & 31;
        int f = k >> 4, i = k & 15;
        g_W1p[idx] = We1[((o << 4) + i) * 8 + f];
    }
    int j = idx - 128 * 32;
    if (j >= 0 && j < 256 * 64) {         // W2p[k=f*32+i][o] = We2[(o*32+i)*8+f]
        int k = j >> 6, o = j & 63;
        int f = k >> 5, i = k & 31;
        g_W2p[j] = We2[((o << 5) + i) * 8 + f];
    }
    int p = idx - (128 * 32 + 256 * 64);
    if (p >= 0 && p < 64 * 128) {
        int i = p >> 7, o = p & 127;
        g_Wt1[p] = Wf1[o * 64 + i];
    }
    int q = idx - (128 * 32 + 256 * 64 + 64 * 128);
    if (q >= 0 && q < 128 * 128) {
        int i = q >> 7, o = q & 127;
        g_Wt2[q] = Wf2[o * 128 + i];
    }
}

// ---------------- out-degree ----------------
__global__ void k_deg(const int* __restrict__ ei) {
    int e = blockIdx.x * blockDim.x + threadIdx.x;
    if (e < NE) atomicAdd(&g_deg[ei[e]], 1);
}

// ---------------- edge scatter layer 1: T1[d][f*16+i] += ea[e,f]*xn[s,i] ----
__global__ __launch_bounds__(256) void k_scat1(const int* __restrict__ ei,
                                               const float* __restrict__ ea,
                                               const float* __restrict__ x) {
    int idx = blockIdx.x * 256 + threadIdx.x;
    if (idx >= NE * 8) return;
    int e = idx >> 3, f = idx & 7;
    int s = __ldg(ei + e), d = __ldg(ei + NE + e);
    float nrm = 1.0f / (float)g_deg[s];
    float z = __ldg(ea + (size_t)e * 8 + f) * nrm;
    const float4* xp = (const float4*)(x + (size_t)s * 16);
    float* dst = g_T1 + (size_t)d * 128 + f * 16;
    #pragma unroll
    for (int q = 0; q < 4; q++) {
        float4 v = __ldg(xp + q);
        red_v4(dst + q * 4, make_float4(z * v.x, z * v.y, z * v.z, z * v.w));
    }
}

// ---------------- edge scatter layer 2: T2[d][f*32+i] += ea[e,f]*h1n[s,i] ---
__global__ __launch_bounds__(256) void k_scat2(const int* __restrict__ ei,
                                               const float* __restrict__ ea) {
    int idx = blockIdx.x * 256 + threadIdx.x;
    if (idx >= NE * 8) return;
    int e = idx >> 3, f = idx & 7;
    int s = __ldg(ei + e), d = __ldg(ei + NE + e);
    float nrm = 1.0f / (float)g_deg[s];
    float z = __ldg(ea + (size_t)e * 8 + f) * nrm;
    const float4* hp = (const float4*)(g_h1n + (size_t)s * 32);
    float* dst = g_T2 + (size_t)d * 256 + f * 32;
    #pragma unroll
    for (int q = 0; q < 8; q++) {
        float4 v = hp[q];
        red_v4(dst + q * 4, make_float4(z * v.x, z * v.y, z * v.z, z * v.w));
    }
}

// ---------------- GEMM layer1: h1 = T1@W1p + x@Wr1^T + b1 ; stats1 ----------
// block: 128 threads = 16 tn x 8 to; tile: 128 nodes x 32 outs; thread: 8n x 4o
__global__ __launch_bounds__(128) void k_gemm_l1(const float* __restrict__ x,
                                                 const float* __restrict__ Wr1,
                                                 const float* __restrict__ b1) {
    __shared__ float As[32 * 132];
    __shared__ float Bs[32 * 32];
    __shared__ float s_sum[32], s_sq[32];
    int tid = threadIdx.x;
    if (tid < 32) { s_sum[tid] = 0.f; s_sq[tid] = 0.f; }
    int n0 = blockIdx.x * 128;
    int tn = tid >> 3, to = tid & 7;

    float acc[8][4];
    #pragma unroll
    for (int m = 0; m < 8; m++)
        #pragma unroll
        for (int j = 0; j < 4; j++) acc[m][j] = 0.f;

    // main K = 128, 4 stages of 32
    for (int ks = 0; ks < 4; ks++) {
        __syncthreads();
        int kq = tid & 7, rr = tid >> 3;    // 16 rows per iter, 8 iters
        #pragma unroll
        for (int it = 0; it < 8; it++) {
            int row = it * 16 + rr;
            int gn = n0 + row;
            float4 v = make_float4(0, 0, 0, 0);
            if (gn < NN) v = *(const float4*)(g_T1 + (size_t)gn * 128 + ks * 32 + kq * 4);
            As[(kq * 4 + 0) * 132 + row] = v.x;
            As[(kq * 4 + 1) * 132 + row] = v.y;
            As[(kq * 4 + 2) * 132 + row] = v.z;
            As[(kq * 4 + 3) * 132 + row] = v.w;
        }
        for (int t = tid; t < 32 * 32; t += 128) Bs[t] = g_W1p[ks * 32 * 32 + t];
        __syncthreads();
        #pragma unroll
        for (int k = 0; k < 32; k++) {
            float4 b = *(const float4*)(Bs + k * 32 + to * 4);
            float4 a0 = *(const float4*)(As + k * 132 + tn * 8);
            float4 a1 = *(const float4*)(As + k * 132 + tn * 8 + 4);
            const float av[8] = {a0.x, a0.y, a0.z, a0.w, a1.x, a1.y, a1.z, a1.w};
            #pragma unroll
            for (int m = 0; m < 8; m++) {
                acc[m][0] += av[m] * b.x; acc[m][1] += av[m] * b.y;
                acc[m][2] += av[m] * b.z; acc[m][3] += av[m] * b.w;
            }
        }
    }
    // aux K = 16: x @ Wr1^T
    {
        __syncthreads();
        int kq = tid & 3, rr = tid >> 2;    // 32 rows per iter, 4 iters
        #pragma unroll
        for (int it = 0; it < 4; it++) {
            int row = it * 32 + rr;
            int gn = n0 + row;
            float4 v = make_float4(0, 0, 0, 0);
            if (gn < NN) v = *(const float4*)(x + (size_t)gn * 16 + kq * 4);
            As[(kq * 4 + 0) * 132 + row] = v.x;
            As[(kq * 4 + 1) * 132 + row] = v.y;
            As[(kq * 4 + 2) * 132 + row] = v.z;
            As[(kq * 4 + 3) * 132 + row] = v.w;
        }
        for (int t = tid; t < 512; t += 128) {
            int o = t & 31, k = t >> 5;
            Bs[k * 32 + o] = Wr1[o * 16 + k];
        }
        __syncthreads();
        #pragma unroll
        for (int k = 0; k < 16; k++) {
            float4 b = *(const float4*)(Bs + k * 32 + to * 4);
            float4 a0 = *(const float4*)(As + k * 132 + tn * 8);
            float4 a1 = *(const float4*)(As + k * 132 + tn * 8 + 4);
            const float av[8] = {a0.x, a0.y, a0.z, a0.w, a1.x, a1.y, a1.z, a1.w};
            #pragma unroll
            for (int m = 0; m < 8; m++) {
                acc[m][0] += av[m] * b.x; acc[m][1] += av[m] * b.y;
                acc[m][2] += av[m] * b.z; acc[m][3] += av[m] * b.w;
            }
        }
    }
    // epilogue: bias, write h1, stats
    float bv[4];
    #pragma unroll
    for (int j = 0; j < 4; j++) bv[j] = __ldg(b1 + to * 4 + j);
    float ls[4] = {0, 0, 0, 0}, lq[4] = {0, 0, 0, 0};
    #pragma unroll
    for (int m = 0; m < 8; m++) {
        int gn = n0 + tn * 8 + m;
        if (gn < NN) {
            float4 h;
            h.x = acc[m][0] + bv[0]; h.y = acc[m][1] + bv[1];
            h.z = acc[m][2] + bv[2]; h.w = acc[m][3] + bv[3];
            *(float4*)(g_h1 + (size_t)gn * 32 + to * 4) = h;
            ls[0] += h.x; ls[1] += h.y; ls[2] += h.z; ls[3] += h.w;
            lq[0] += h.x * h.x; lq[1] += h.y * h.y; lq[2] += h.z * h.z; lq[3] += h.w * h.w;
        }
    }
    #pragma unroll
    for (int j = 0; j < 4; j++) {
        atomicAdd(&s_sum[to * 4 + j], ls[j]);
        atomicAdd(&s_sq [to * 4 + j], lq[j]);
    }
    __syncthreads();
    if (tid < 32) {
        atomicAdd(&g_stat1[tid],      s_sum[tid]);
        atomicAdd(&g_stat1[32 + tid], s_sq[tid]);
    }
}

// ---------------- GEMM layer2: h2 = T2@W2p + h1n@Wr2^T + b2 ; stats2 --------
// block: 256 threads = 16 tn x 16 to; tile: 128 nodes x 64 outs; thread: 8n x 4o
__global__ __launch_bounds__(256) void k_gemm_l2(const float* __restrict__ Wr2,
                                                 const float* __restrict__ b2) {
    __shared__ float As[32 * 132];
    __shared__ float Bs[32 * 64];
    __shared__ float s_sum[64], s_sq[64];
    int tid = threadIdx.x;
    if (tid < 64) { s_sum[tid] = 0.f; s_sq[tid] = 0.f; }
    int n0 = blockIdx.x * 128;
    int tn = tid >> 4, to = tid & 15;

    float acc[8][4];
    #pragma unroll
    for (int m = 0; m < 8; m++)
        #pragma unroll
        for (int j = 0; j < 4; j++) acc[m][j] = 0.f;

    // main K = 256, 8 stages of 32
    for (int ks = 0; ks < 8; ks++) {
        __syncthreads();
        int kq = tid & 7, rr = tid >> 3;    // 32 rows per iter, 4 iters
        #pragma unroll
        for (int it = 0; it < 4; it++) {
            int row = it * 32 + rr;
            int gn = n0 + row;
            float4 v = make_float4(0, 0, 0, 0);
            if (gn < NN) v = *(const float4*)(g_T2 + (size_t)gn * 256 + ks * 32 + kq * 4);
            As[(kq * 4 + 0) * 132 + row] = v.x;
            As[(kq * 4 + 1) * 132 + row] = v.y;
            As[(kq * 4 + 2) * 132 + row] = v.z;
            As[(kq * 4 + 3) * 132 + row] = v.w;
        }
        for (int t = tid; t < 32 * 64; t += 256) Bs[t] = g_W2p[ks * 32 * 64 + t];
        __syncthreads();
        #pragma unroll
        for (int k = 0; k < 32; k++) {
            float4 b = *(const float4*)(Bs + k * 64 + to * 4);
            float4 a0 = *(const float4*)(As + k * 132 + tn * 8);
            float4 a1 = *(const float4*)(As + k * 132 + tn * 8 + 4);
            const float av[8] = {a0.x, a0.y, a0.z, a0.w, a1.x, a1.y, a1.z, a1.w};
            #pragma unroll
            for (int m = 0; m < 8; m++) {
                acc[m][0] += av[m] * b.x; acc[m][1] += av[m] * b.y;
                acc[m][2] += av[m] * b.z; acc[m][3] += av[m] * b.w;
            }
        }
    }
    // aux K = 32: h1n @ Wr2^T
    {
        __syncthreads();
        int kq = tid & 7, rr = tid >> 3;
        #pragma unroll
        for (int it = 0; it < 4; it++) {
            int row = it * 32 + rr;
            int gn = n0 + row;
            float4 v = make_float4(0, 0, 0, 0);
            if (gn < NN) v = *(const float4*)(g_h1n + (size_t)gn * 32 + kq * 4);
            As[(kq * 4 + 0) * 132 + row] = v.x;
            As[(kq * 4 + 1) * 132 + row] = v.y;
            As[(kq * 4 + 2) * 132 + row] = v.z;
            As[(kq * 4 + 3) * 132 + row] = v.w;
        }
        for (int t = tid; t < 2048; t += 256) {
            int o = t & 63, k = t >> 6;
            Bs[k * 64 + o] = Wr2[o * 32 + k];
        }
        __syncthreads();
        #pragma unroll
        for (int k = 0; k < 32; k++) {
            float4 b = *(const float4*)(Bs + k * 64 + to * 4);
            float4 a0 = *(const float4*)(As + k * 132 + tn * 8);
            float4 a1 = *(const float4*)(As + k * 132 + tn * 8 + 4);
            const float av[8] = {a0.x, a0.y, a0.z, a0.w, a1.x, a1.y, a1.z, a1.w};
            #pragma unroll
            for (int m = 0; m < 8; m++) {
                acc[m][0] += av[m] * b.x; acc[m][1] += av[m] * b.y;
                acc[m][2] += av[m] * b.z; acc[m][3] += av[m] * b.w;
            }
        }
    }
    // epilogue
    float bv[4];
    #pragma unroll
    for (int j = 0; j < 4; j++) bv[j] = __ldg(b2 + to * 4 + j);
    float ls[4] = {0, 0, 0, 0}, lq[4] = {0, 0, 0, 0};
    #pragma unroll
    for (int m = 0; m < 8; m++) {
        int gn = n0 + tn * 8 + m;
        if (gn < NN) {
            float4 h;
            h.x = acc[m][0] + bv[0]; h.y = acc[m][1] + bv[1];
            h.z = acc[m][2] + bv[2]; h.w = acc[m][3] + bv[3];
            *(float4*)(g_h2 + (size_t)gn * 64 + to * 4) = h;
            ls[0] += h.x; ls[1] += h.y; ls[2] += h.z; ls[3] += h.w;
            lq[0] += h.x * h.x; lq[1] += h.y * h.y; lq[2] += h.z * h.z; lq[3] += h.w * h.w;
        }
    }
    #pragma unroll
    for (int j = 0; j < 4; j++) {
        atomicAdd(&s_sum[to * 4 + j], ls[j]);
        atomicAdd(&s_sq [to * 4 + j], lq[j]);
    }
    __syncthreads();
    if (tid < 64) {
        atomicAdd(&g_stat2[tid],      s_sum[tid]);
        atomicAdd(&g_stat2[64 + tid], s_sq[tid]);
    }
}

// ---------------- BN1 apply + relu -> h1n (vectorized) ----------------
__global__ void k_bn1(const float* __restrict__ g1, const float* __restrict__ be1) {
    int idx = blockIdx.x * blockDim.x + threadIdx.x;
    if (idx >= NN * 8) return;
    int n = idx >> 3, q = idx & 7;
    const float invN = 1.0f / (float)NN;
    float4 h = *(const float4*)(g_h1 + (size_t)n * 32 + q * 4);
    float4 v;
    float* hv = (float*)&h; float* vv = (float*)&v;
    #pragma unroll
    for (int j = 0; j < 4; j++) {
        int c = q * 4 + j;
        float mu = g_stat1[c] * invN;
        float var = g_stat1[32 + c] * invN - mu * mu;
        float rs = rsqrtf(var + EPSV);
        vv[j] = fmaxf((hv[j] - mu) * rs * __ldg(g1 + c) + __ldg(be1 + c), 0.f);
    }
    *(float4*)(g_h1n + (size_t)n * 32 + q * 4) = v;
}

// ---------------- BN2 apply + relu + pooling ----------------
__global__ void k_bn2pool(const float* __restrict__ g2, const float* __restrict__ be2,
                          const int* __restrict__ batch) {
    int idx = blockIdx.x * blockDim.x + threadIdx.x;
    if (idx >= NN * 16) return;
    int n = idx >> 4, q = idx & 15;
    const float invN = 1.0f / (float)NN;
    float4 h = *(const float4*)(g_h2 + (size_t)n * 64 + q * 4);
    float4 v;
    float* hv = (float*)&h; float* vv = (float*)&v;
    #pragma unroll
    for (int j = 0; j < 4; j++) {
        int c = q * 4 + j;
        float mu = g_stat2[c] * invN;
        float var = g_stat2[64 + c] * invN - mu * mu;
        float rs = rsqrtf(var + EPSV);
        vv[j] = fmaxf((hv[j] - mu) * rs * __ldg(g2 + c) + __ldg(be2 + c), 0.f);
    }
    int b = batch[n];
    red_v4(g_pooled + (size_t)b * 64 + q * 4, v);
    if (q == 0) atomicAdd(&g_cnt[b], 1.0f);
}

// ---------------- final MLP: 8 graphs per block ----------------
__global__ __launch_bounds__(128) void k_fc(const float* __restrict__ bf1,
                                            const float* __restrict__ bf2,
                                            float* __restrict__ out) {
    __shared__ float pm[8][64];
    __shared__ float hid[8][128];
    int tid = threadIdx.x;
    int g0 = blockIdx.x * 8;
    for (int t = tid; t < 512; t += 128) {
        int gg = t >> 6, i = t & 63;
        int g = g0 + gg;
        pm[gg][i] = g_pooled[g * 64 + i] / fmaxf(g_cnt[g], 1.0f);
    }
    __syncthreads();

    float acc[8];
    float b = bf1[tid];
    #pragma unroll
    for (int gg = 0; gg < 8; gg++) acc[gg] = b;
    for (int i = 0; i < 64; i++) {
        float w = g_Wt1[i * 128 + tid];
        #pragma unroll
        for (int gg = 0; gg < 8; gg++) acc[gg] += w * pm[gg][i];
    }
    #pragma unroll
    for (int gg = 0; gg < 8; gg++) hid[gg][tid] = fmaxf(acc[gg], 0.f);
    __syncthreads();

    float b2v = bf2[tid];
    #pragma unroll
    for (int gg = 0; gg < 8; gg++) acc[gg] = b2v;
    for (int i = 0; i < 128; i++) {
        float w = g_Wt2[i * 128 + tid];
        #pragma unroll
        for (int gg = 0; gg < 8; gg++) acc[gg] += w * hid[gg][i];
    }
    #pragma unroll
    for (int gg = 0; gg < 8; gg++) {
        int g = g0 + gg;
        if (tid < 64) out[g * 64 + tid] = acc[gg];
        else          out[NG * 64 + g * 64 + (tid - 64)] = acc[gg];
    }
}

// ---------------- launch ----------------
extern "C" void kernel_launch(void* const* d_in, const int* in_sizes, int n_in,
                              void* d_out, int out_size) {
    const float* x    = (const float*)d_in[0];
    const int*   ei   = (const int*)  d_in[1];
    const float* ea   = (const float*)d_in[2];
    const int*   batch= (const int*)  d_in[3];
    const float* We1  = (const float*)d_in[4];
    const float* b1   = (const float*)d_in[5];
    const float* Wr1  = (const float*)d_in[6];
    const float* g1   = (const float*)d_in[7];
    const float* be1  = (const float*)d_in[8];
    const float* We2  = (const float*)d_in[9];
    const float* b2   = (const float*)d_in[10];
    const float* Wr2  = (const float*)d_in[11];
    const float* g2   = (const float*)d_in[12];
    const float* be2  = (const float*)d_in[13];
    const float* Wf1  = (const float*)d_in[14];
    const float* bf1  = (const float*)d_in[15];
    const float* Wf2  = (const float*)d_in[16];
    const float* bf2  = (const float*)d_in[17];
    float* out = (float*)d_out;

    static float* pT1 = nullptr;
    static float* pT2 = nullptr;
    if (!pT1) {
        cudaGetSymbolAddress((void**)&pT1, g_T1);
        cudaGetSymbolAddress((void**)&pT2, g_T2);
    }

    cudaMemsetAsync(pT1, 0, sizeof(float) * (size_t)NN * 128, 0);
    cudaMemsetAsync(pT2, 0, sizeof(float) * (size_t)NN * 256, 0);
    k_init<<<256, 256>>>();
    k_prep<<<(128 * 32 + 256 * 64 + 64 * 128 + 128 * 128 + 255) / 256, 256>>>(We1, We2, Wf1, Wf2);
    k_deg<<<(NE + 255) / 256, 256>>>(ei);
    k_scat1<<<(NE * 8 + 255) / 256, 256>>>(ei, ea, x);
    k_gemm_l1<<<(NN + 127) / 128, 128>>>(x, Wr1, b1);
    k_bn1<<<(NN * 8 + 255) / 256, 256>>>(g1, be1);
    k_scat2<<<(NE * 8 + 255) / 256, 256>>>(ei, ea);
    k_gemm_l2<<<(NN + 127) / 128, 256>>>(Wr2, b2);
    k_bn2pool<<<(NN * 16 + 255) / 256, 256>>>(g2, be2, batch);
    k_fc<<<NG / 8, 128>>>(bf1, bf2, out);
}